// round 1
// baseline (speedup 1.0000x reference)
#include <cuda_runtime.h>
#include <cstdint>

#define NE 50000
#define EDGES 500000
#define NREL 200
#define RANK 128
#define SLOPE 0.22916666666666666f   // (1/8 + 1/3)/2

// ---------------- scratch (device globals; no allocation allowed) ----------------
__device__ float g_h2[NE * RANK];    // hidden state after layer 0
__device__ float g_acc[NE * RANK];   // scatter accumulator
__device__ int   g_hasin[NE];        // in-degree > 0 mask

// ---------------- kernels ----------------

__global__ void mark_hasin_kernel(const int* __restrict__ dst, int* __restrict__ hasin) {
    int i = blockIdx.x * blockDim.x + threadIdx.x;
    if (i < EDGES) hasin[dst[i]] = 1;
}

// acc[dst] += h[src] + rel[etype]   (one warp per edge, red.global.v4.f32)
__global__ void scatter_kernel(const float* __restrict__ h,
                               const float* __restrict__ rel,
                               const int* __restrict__ src,
                               const int* __restrict__ dst,
                               const int* __restrict__ et,
                               float* __restrict__ acc) {
    int lane  = threadIdx.x & 31;
    int warp  = (blockIdx.x * blockDim.x + threadIdx.x) >> 5;
    int nwarp = (gridDim.x * blockDim.x) >> 5;
    int col   = lane * 4;
    for (int e = warp; e < EDGES; e += nwarp) {
        int s = src[e], d = dst[e], t = et[e];
        float4 hv = *(const float4*)(h   + (size_t)s * RANK + col);
        float4 rv = *(const float4*)(rel + (size_t)t * RANK + col);
        float4 v;
        v.x = hv.x + rv.x; v.y = hv.y + rv.y; v.z = hv.z + rv.z; v.w = hv.w + rv.w;
        float* p = acc + (size_t)d * RANK + col;
        asm volatile("red.global.add.v4.f32 [%0], {%1, %2, %3, %4};"
                     :: "l"(p), "f"(v.x), "f"(v.y), "f"(v.z), "f"(v.w) : "memory");
    }
}

// out = leaky( norm * (A @ Wn) + B @ Wl ), A=acc, B=h. BM=64 rows per block.
#define BM 64
#define KC 16
#define APAD (BM + 4)
__global__ __launch_bounds__(256) void gemm_combine_kernel(
    const float* __restrict__ A,
    const float* __restrict__ B,
    const float* __restrict__ Wn,   // [128][128] row index = k
    const float* __restrict__ Wl,
    const float* __restrict__ norm,
    float* __restrict__ out) {

    __shared__ float As[KC][APAD];
    __shared__ float Bs[KC][APAD];
    __shared__ float Wns[KC][RANK];
    __shared__ float Wls[KC][RANK];

    int tid  = threadIdx.x;
    int c    = tid & 15;    // col group: cols c*8 .. c*8+7
    int r    = tid >> 4;    // row group: rows r*4 .. r*4+3
    int row0 = blockIdx.x * BM;

    float accA[4][8], accB[4][8];
#pragma unroll
    for (int i = 0; i < 4; i++)
#pragma unroll
        for (int j = 0; j < 8; j++) { accA[i][j] = 0.f; accB[i][j] = 0.f; }

    int lr = tid >> 2;            // 0..63 : row within tile to load
    int lq = (tid & 3) * 4;       // k sub-offset

    for (int kc = 0; kc < RANK; kc += KC) {
        int grow = row0 + lr;
        float4 av = make_float4(0.f, 0.f, 0.f, 0.f);
        float4 bv = make_float4(0.f, 0.f, 0.f, 0.f);
        if (grow < NE) {
            av = *(const float4*)(A + (size_t)grow * RANK + kc + lq);
            bv = *(const float4*)(B + (size_t)grow * RANK + kc + lq);
        }
        As[lq + 0][lr] = av.x; As[lq + 1][lr] = av.y; As[lq + 2][lr] = av.z; As[lq + 3][lr] = av.w;
        Bs[lq + 0][lr] = bv.x; Bs[lq + 1][lr] = bv.y; Bs[lq + 2][lr] = bv.z; Bs[lq + 3][lr] = bv.w;

        const float4* wn4 = (const float4*)(Wn + (size_t)kc * RANK);
        const float4* wl4 = (const float4*)(Wl + (size_t)kc * RANK);
        ((float4*)&Wns[0][0])[tid]       = wn4[tid];
        ((float4*)&Wns[0][0])[tid + 256] = wn4[tid + 256];
        ((float4*)&Wls[0][0])[tid]       = wl4[tid];
        ((float4*)&Wls[0][0])[tid + 256] = wl4[tid + 256];
        __syncthreads();

#pragma unroll
        for (int k = 0; k < KC; k++) {
            float4 a4 = *(const float4*)&As[k][r * 4];
            float4 b4 = *(const float4*)&Bs[k][r * 4];
            float4 w0 = *(const float4*)&Wns[k][c * 8];
            float4 w1 = *(const float4*)&Wns[k][c * 8 + 4];
            float4 u0 = *(const float4*)&Wls[k][c * 8];
            float4 u1 = *(const float4*)&Wls[k][c * 8 + 4];
            float a[4] = {a4.x, a4.y, a4.z, a4.w};
            float b[4] = {b4.x, b4.y, b4.z, b4.w};
            float wn[8] = {w0.x, w0.y, w0.z, w0.w, w1.x, w1.y, w1.z, w1.w};
            float wl[8] = {u0.x, u0.y, u0.z, u0.w, u1.x, u1.y, u1.z, u1.w};
#pragma unroll
            for (int i = 0; i < 4; i++)
#pragma unroll
                for (int j = 0; j < 8; j++) {
                    accA[i][j] = fmaf(a[i], wn[j], accA[i][j]);
                    accB[i][j] = fmaf(b[i], wl[j], accB[i][j]);
                }
        }
        __syncthreads();
    }

#pragma unroll
    for (int i = 0; i < 4; i++) {
        int row = row0 + r * 4 + i;
        if (row >= NE) continue;
        float nv = norm[row];
        float v[8];
#pragma unroll
        for (int j = 0; j < 8; j++) {
            float x = fmaf(nv, accA[i][j], accB[i][j]);
            v[j] = (x >= 0.f) ? x : x * SLOPE;
        }
        float* o = out + (size_t)row * RANK + c * 8;
        *(float4*)(o)     = make_float4(v[0], v[1], v[2], v[3]);
        *(float4*)(o + 4) = make_float4(v[4], v[5], v[6], v[7]);
    }
}

// Rows with in_deg==0 (expected ~2 of 50000): out[row] = leaky(h[row] @ Wa)
__global__ void fixup_kernel(const float* __restrict__ B,
                             const float* __restrict__ Wa,
                             const int* __restrict__ hasin,
                             float* __restrict__ out) {
    int lane  = threadIdx.x & 31;
    int warp  = (blockIdx.x * blockDim.x + threadIdx.x) >> 5;
    int nwarp = (gridDim.x * blockDim.x) >> 5;
    for (int row = warp; row < NE; row += nwarp) {
        if (hasin[row]) continue;
        float acc0 = 0.f, acc1 = 0.f, acc2 = 0.f, acc3 = 0.f;
        const float* brow = B + (size_t)row * RANK;
#pragma unroll 4
        for (int k = 0; k < RANK; k++) {
            float hk = __ldg(brow + k);
            float4 w = *(const float4*)(Wa + (size_t)k * RANK + lane * 4);
            acc0 = fmaf(hk, w.x, acc0);
            acc1 = fmaf(hk, w.y, acc1);
            acc2 = fmaf(hk, w.z, acc2);
            acc3 = fmaf(hk, w.w, acc3);
        }
        float4 v;
        v.x = (acc0 >= 0.f) ? acc0 : acc0 * SLOPE;
        v.y = (acc1 >= 0.f) ? acc1 : acc1 * SLOPE;
        v.z = (acc2 >= 0.f) ? acc2 : acc2 * SLOPE;
        v.w = (acc3 >= 0.f) ? acc3 : acc3 * SLOPE;
        *(float4*)(out + (size_t)row * RANK + lane * 4) = v;
    }
}

// ---------------- launch ----------------
extern "C" void kernel_launch(void* const* d_in, const int* in_sizes, int n_in,
                              void* d_out, int out_size) {
    const float* ent  = (const float*)d_in[0];
    const float* rel  = (const float*)d_in[1];
    const float* norm = (const float*)d_in[2];
    const float* Wn   = (const float*)d_in[3];
    const float* Wl   = (const float*)d_in[4];
    const float* Wa   = (const float*)d_in[5];
    const int*   src  = (const int*)d_in[6];
    const int*   dst  = (const int*)d_in[7];
    const int*   et   = (const int*)d_in[8];
    float* out = (float*)d_out;

    void *p_h2, *p_acc, *p_hasin;
    cudaGetSymbolAddress(&p_h2, g_h2);
    cudaGetSymbolAddress(&p_acc, g_acc);
    cudaGetSymbolAddress(&p_hasin, g_hasin);
    float* h2  = (float*)p_h2;
    float* acc = (float*)p_acc;
    int* hasin = (int*)p_hasin;

    const int WOFF = RANK * RANK;  // per-layer weight offset

    cudaMemsetAsync(hasin, 0, NE * sizeof(int), 0);
    mark_hasin_kernel<<<(EDGES + 255) / 256, 256>>>(dst, hasin);

    const int gemm_blocks = (NE + BM - 1) / BM;

    // ---- layer 0: h = ent_emb ----
    cudaMemsetAsync(acc, 0, (size_t)NE * RANK * sizeof(float), 0);
    scatter_kernel<<<2048, 256>>>(ent, rel, src, dst, et, acc);
    gemm_combine_kernel<<<gemm_blocks, 256>>>(acc, ent, Wn, Wl, norm, h2);
    fixup_kernel<<<512, 256>>>(ent, Wa, hasin, h2);

    // ---- layer 1: h = h2, write final output ----
    cudaMemsetAsync(acc, 0, (size_t)NE * RANK * sizeof(float), 0);
    scatter_kernel<<<2048, 256>>>(h2, rel, src, dst, et, acc);
    gemm_combine_kernel<<<gemm_blocks, 256>>>(acc, h2, Wn + WOFF, Wl + WOFF, norm, out);
    fixup_kernel<<<512, 256>>>(h2, Wa + WOFF, hasin, out);
}

// round 3
// speedup vs baseline: 1.2552x; 1.2552x over previous
#include <cuda_runtime.h>
#include <cstdint>

#define NE 50000
#define EDGES 500000
#define NREL 200
#define RANK 128
#define SLOPE 0.22916666666666666f   // (1/8 + 1/3)/2

// ---------------- scratch (device globals; no allocation allowed) ----------------
__device__ float g_h2[NE * RANK];    // hidden state after layer 0
__device__ float g_acc[NE * RANK];   // scatter accumulator
__device__ int   g_hasin[NE];        // in-degree > 0 mask
__device__ int   g_zlist[NE];        // rows with in-degree == 0
__device__ int   g_zcount;

// ---------------- f32x2 helpers (sm_103a packed fp32) ----------------
__device__ __forceinline__ unsigned long long pack2(float x) {
    unsigned long long r;
    asm("mov.b64 %0, {%1, %1};" : "=l"(r) : "f"(x));
    return r;
}
__device__ __forceinline__ void ffma2(unsigned long long& c,
                                      unsigned long long a,
                                      unsigned long long b) {
    asm("fma.rn.f32x2 %0, %1, %2, %0;" : "+l"(c) : "l"(a), "l"(b));
}
__device__ __forceinline__ float2 unpack2(unsigned long long v) {
    float2 f;
    asm("mov.b64 {%0, %1}, %2;" : "=f"(f.x), "=f"(f.y) : "l"(v));
    return f;
}

// ---------------- kernels ----------------

__global__ void mark_hasin_kernel(const int* __restrict__ dst, int* __restrict__ hasin) {
    int i = blockIdx.x * blockDim.x + threadIdx.x;
    if (i < EDGES) hasin[dst[i]] = 1;
}

__global__ void build_zlist_kernel(const int* __restrict__ hasin,
                                   int* __restrict__ zlist, int* __restrict__ zcount) {
    int i = blockIdx.x * blockDim.x + threadIdx.x;
    if (i < NE && !hasin[i]) {
        int p = atomicAdd(zcount, 1);
        zlist[p] = i;
    }
}

// acc[dst] += h[src] + rel[etype]   (one warp per edge, red.global.v4.f32)
__global__ void scatter_kernel(const float* __restrict__ h,
                               const float* __restrict__ rel,
                               const int* __restrict__ src,
                               const int* __restrict__ dst,
                               const int* __restrict__ et,
                               float* __restrict__ acc) {
    int lane  = threadIdx.x & 31;
    int warp  = (blockIdx.x * blockDim.x + threadIdx.x) >> 5;
    int nwarp = (gridDim.x * blockDim.x) >> 5;
    int col   = lane * 4;
    for (int e = warp; e < EDGES; e += nwarp) {
        int s = src[e], d = dst[e], t = et[e];
        float4 hv = *(const float4*)(h   + (size_t)s * RANK + col);
        float4 rv = *(const float4*)(rel + (size_t)t * RANK + col);
        float4 v;
        v.x = hv.x + rv.x; v.y = hv.y + rv.y; v.z = hv.z + rv.z; v.w = hv.w + rv.w;
        float* p = acc + (size_t)d * RANK + col;
        asm volatile("red.global.add.v4.f32 [%0], {%1, %2, %3, %4};"
                     :: "l"(p), "f"(v.x), "f"(v.y), "f"(v.z), "f"(v.w) : "memory");
    }
}

// out = leaky( (norm*A) @ Wn + B @ Wl ),  A=acc, B=h.  BM=64 rows per block.
// Thread (r,c): rows r*4..r*4+3, column PAIRS p_j = c + 16*j (cols 2p, 2p+1).
// Inner product on fma.rn.f32x2 (2x fp32 throughput); weight LDS.64 reads are
// contiguous 128B per 16 threads -> conflict-free.
#define BM 64
#define KC 16
#define APAD (BM + 4)
__global__ __launch_bounds__(256) void gemm_combine_kernel(
    const float* __restrict__ A,
    const float* __restrict__ B,
    const float* __restrict__ Wn,   // [128][128], row index = k
    const float* __restrict__ Wl,
    const float* __restrict__ norm,
    float* __restrict__ out) {

    __shared__ float As[KC][APAD];
    __shared__ float Bs[KC][APAD];
    __shared__ float Wns[KC][RANK];
    __shared__ float Wls[KC][RANK];

    int tid  = threadIdx.x;
    int c    = tid & 15;    // pair-group id
    int r    = tid >> 4;    // row group: rows r*4 .. r*4+3
    int row0 = blockIdx.x * BM;

    unsigned long long accA2[4][4], accB2[4][4];
#pragma unroll
    for (int i = 0; i < 4; i++)
#pragma unroll
        for (int j = 0; j < 4; j++) { accA2[i][j] = 0ull; accB2[i][j] = 0ull; }

    int lr = tid >> 2;            // 0..63 : row within tile to load
    int lq = (tid & 3) * 4;       // k sub-offset
    int grow = row0 + lr;
    float nv_l = (grow < NE) ? norm[grow] : 0.f;

    for (int kc = 0; kc < RANK; kc += KC) {
        float4 av = make_float4(0.f, 0.f, 0.f, 0.f);
        float4 bv = make_float4(0.f, 0.f, 0.f, 0.f);
        if (grow < NE) {
            av = *(const float4*)(A + (size_t)grow * RANK + kc + lq);
            bv = *(const float4*)(B + (size_t)grow * RANK + kc + lq);
        }
        // fold norm into A tile: norm*(acc@Wn) == (norm*acc)@Wn
        av.x *= nv_l; av.y *= nv_l; av.z *= nv_l; av.w *= nv_l;
        As[lq + 0][lr] = av.x; As[lq + 1][lr] = av.y; As[lq + 2][lr] = av.z; As[lq + 3][lr] = av.w;
        Bs[lq + 0][lr] = bv.x; Bs[lq + 1][lr] = bv.y; Bs[lq + 2][lr] = bv.z; Bs[lq + 3][lr] = bv.w;

        const float4* wn4 = (const float4*)(Wn + (size_t)kc * RANK);
        const float4* wl4 = (const float4*)(Wl + (size_t)kc * RANK);
        ((float4*)&Wns[0][0])[tid]       = wn4[tid];
        ((float4*)&Wns[0][0])[tid + 256] = wn4[tid + 256];
        ((float4*)&Wls[0][0])[tid]       = wl4[tid];
        ((float4*)&Wls[0][0])[tid + 256] = wl4[tid + 256];
        __syncthreads();

#pragma unroll
        for (int k = 0; k < KC; k++) {
            float4 a4 = *(const float4*)&As[k][r * 4];
            float4 b4 = *(const float4*)&Bs[k][r * 4];
            unsigned long long a2[4] = {pack2(a4.x), pack2(a4.y), pack2(a4.z), pack2(a4.w)};
            unsigned long long b2[4] = {pack2(b4.x), pack2(b4.y), pack2(b4.z), pack2(b4.w)};
            const unsigned long long* wnr = (const unsigned long long*)&Wns[k][0];
            const unsigned long long* wlr = (const unsigned long long*)&Wls[k][0];
            unsigned long long wn2[4], wl2[4];
#pragma unroll
            for (int j = 0; j < 4; j++) {
                wn2[j] = wnr[c + 16 * j];
                wl2[j] = wlr[c + 16 * j];
            }
#pragma unroll
            for (int i = 0; i < 4; i++)
#pragma unroll
                for (int j = 0; j < 4; j++) {
                    ffma2(accA2[i][j], a2[i], wn2[j]);
                    ffma2(accB2[i][j], b2[i], wl2[j]);
                }
        }
        __syncthreads();
    }

#pragma unroll
    for (int i = 0; i < 4; i++) {
        int row = row0 + r * 4 + i;
        if (row >= NE) continue;
        float* o = out + (size_t)row * RANK + 2 * c;
#pragma unroll
        for (int j = 0; j < 4; j++) {
            float2 fa = unpack2(accA2[i][j]);
            float2 fb = unpack2(accB2[i][j]);
            float x = fa.x + fb.x;
            float y = fa.y + fb.y;
            x = (x >= 0.f) ? x : x * SLOPE;
            y = (y >= 0.f) ? y : y * SLOPE;
            *(float2*)(o + 32 * j) = make_float2(x, y);
        }
    }
}

// Rows with in_deg==0 (expected ~2): out[row] = leaky(h[row] @ Wa).
// Iterates only the compact zero-in-degree list.
__global__ void fixup_kernel(const float* __restrict__ B,
                             const float* __restrict__ Wa,
                             const int* __restrict__ zlist,
                             const int* __restrict__ zcount,
                             float* __restrict__ out) {
    int lane  = threadIdx.x & 31;
    int warp  = (blockIdx.x * blockDim.x + threadIdx.x) >> 5;
    int nwarp = (gridDim.x * blockDim.x) >> 5;
    int cnt   = *zcount;
    for (int idx = warp; idx < cnt; idx += nwarp) {
        int row = zlist[idx];
        float acc0 = 0.f, acc1 = 0.f, acc2 = 0.f, acc3 = 0.f;
        const float* brow = B + (size_t)row * RANK;
#pragma unroll 4
        for (int k = 0; k < RANK; k++) {
            float hk = __ldg(brow + k);
            float4 w = *(const float4*)(Wa + (size_t)k * RANK + lane * 4);
            acc0 = fmaf(hk, w.x, acc0);
            acc1 = fmaf(hk, w.y, acc1);
            acc2 = fmaf(hk, w.z, acc2);
            acc3 = fmaf(hk, w.w, acc3);
        }
        float4 v;
        v.x = (acc0 >= 0.f) ? acc0 : acc0 * SLOPE;
        v.y = (acc1 >= 0.f) ? acc1 : acc1 * SLOPE;
        v.z = (acc2 >= 0.f) ? acc2 : acc2 * SLOPE;
        v.w = (acc3 >= 0.f) ? acc3 : acc3 * SLOPE;
        *(float4*)(out + (size_t)row * RANK + lane * 4) = v;
    }
}

// ---------------- launch ----------------
extern "C" void kernel_launch(void* const* d_in, const int* in_sizes, int n_in,
                              void* d_out, int out_size) {
    const float* ent  = (const float*)d_in[0];
    const float* rel  = (const float*)d_in[1];
    const float* norm = (const float*)d_in[2];
    const float* Wn   = (const float*)d_in[3];
    const float* Wl   = (const float*)d_in[4];
    const float* Wa   = (const float*)d_in[5];
    const int*   src  = (const int*)d_in[6];
    const int*   dst  = (const int*)d_in[7];
    const int*   et   = (const int*)d_in[8];
    float* out = (float*)d_out;

    void *p_h2, *p_acc, *p_hasin, *p_zlist, *p_zcount;
    cudaGetSymbolAddress(&p_h2, g_h2);
    cudaGetSymbolAddress(&p_acc, g_acc);
    cudaGetSymbolAddress(&p_hasin, g_hasin);
    cudaGetSymbolAddress(&p_zlist, g_zlist);
    cudaGetSymbolAddress(&p_zcount, g_zcount);
    float* h2   = (float*)p_h2;
    float* acc  = (float*)p_acc;
    int* hasin  = (int*)p_hasin;
    int* zlist  = (int*)p_zlist;
    int* zcount = (int*)p_zcount;

    const int WOFF = RANK * RANK;  // per-layer weight offset

    cudaMemsetAsync(hasin, 0, NE * sizeof(int), 0);
    cudaMemsetAsync(zcount, 0, sizeof(int), 0);
    mark_hasin_kernel<<<(EDGES + 255) / 256, 256>>>(dst, hasin);
    build_zlist_kernel<<<(NE + 255) / 256, 256>>>(hasin, zlist, zcount);

    const int gemm_blocks = (NE + BM - 1) / BM;

    // ---- layer 0: h = ent_emb ----
    cudaMemsetAsync(acc, 0, (size_t)NE * RANK * sizeof(float), 0);
    scatter_kernel<<<2048, 256>>>(ent, rel, src, dst, et, acc);
    gemm_combine_kernel<<<gemm_blocks, 256>>>(acc, ent, Wn, Wl, norm, h2);
    fixup_kernel<<<32, 256>>>(ent, Wa, zlist, zcount, h2);

    // ---- layer 1: h = h2, write final output ----
    cudaMemsetAsync(acc, 0, (size_t)NE * RANK * sizeof(float), 0);
    scatter_kernel<<<2048, 256>>>(h2, rel, src, dst, et, acc);
    gemm_combine_kernel<<<gemm_blocks, 256>>>(acc, h2, Wn + WOFF, Wl + WOFF, norm, out);
    fixup_kernel<<<32, 256>>>(h2, Wa + WOFF, zlist, zcount, out);
}

// round 6
// speedup vs baseline: 1.4131x; 1.1258x over previous
#include <cuda_runtime.h>
#include <cuda_bf16.h>
#include <cstdint>

#define NE 50000
#define EDGES 500000
#define NREL 200
#define RANK 128
#define SLOPE 0.22916666666666666f   // (1/8 + 1/3)/2

// ---------------- scratch (device globals; no allocation allowed) ----------------
__device__ float g_h2[NE * RANK];    // hidden state after layer 0
__device__ float g_acc[NE * RANK];   // scatter accumulator
__device__ int   g_hasin[NE];        // in-degree > 0 mask
__device__ int   g_zlist[NE];        // rows with in-degree == 0
__device__ int   g_zcount;

// ======================= small helper kernels =======================

__global__ void mark_hasin_kernel(const int* __restrict__ dst, int* __restrict__ hasin) {
    int i = blockIdx.x * blockDim.x + threadIdx.x;
    if (i < EDGES) hasin[dst[i]] = 1;
}

__global__ void build_zlist_kernel(const int* __restrict__ hasin,
                                   int* __restrict__ zlist, int* __restrict__ zcount) {
    int i = blockIdx.x * blockDim.x + threadIdx.x;
    if (i < NE && !hasin[i]) {
        int p = atomicAdd(zcount, 1);
        zlist[p] = i;
    }
}

// acc[dst] += h[src] + rel[etype]   (one warp per edge, red.global.v4.f32)
__global__ void scatter_kernel(const float* __restrict__ h,
                               const float* __restrict__ rel,
                               const int* __restrict__ src,
                               const int* __restrict__ dst,
                               const int* __restrict__ et,
                               float* __restrict__ acc) {
    int lane  = threadIdx.x & 31;
    int warp  = (blockIdx.x * blockDim.x + threadIdx.x) >> 5;
    int nwarp = (gridDim.x * blockDim.x) >> 5;
    int col   = lane * 4;
    for (int e = warp; e < EDGES; e += nwarp) {
        int s = src[e], d = dst[e], t = et[e];
        float4 hv = *(const float4*)(h   + (size_t)s * RANK + col);
        float4 rv = *(const float4*)(rel + (size_t)t * RANK + col);
        float4 v;
        v.x = hv.x + rv.x; v.y = hv.y + rv.y; v.z = hv.z + rv.z; v.w = hv.w + rv.w;
        float* p = acc + (size_t)d * RANK + col;
        asm volatile("red.global.add.v4.f32 [%0], {%1, %2, %3, %4};"
                     :: "l"(p), "f"(v.x), "f"(v.y), "f"(v.z), "f"(v.w) : "memory");
    }
}

// Rows with in_deg==0 (expected ~2): out[row] = leaky(h[row] @ Wa)
__global__ void fixup_kernel(const float* __restrict__ B,
                             const float* __restrict__ Wa,
                             const int* __restrict__ zlist,
                             const int* __restrict__ zcount,
                             float* __restrict__ out) {
    int lane  = threadIdx.x & 31;
    int warp  = (blockIdx.x * blockDim.x + threadIdx.x) >> 5;
    int nwarp = (gridDim.x * blockDim.x) >> 5;
    int cnt   = *zcount;
    for (int idx = warp; idx < cnt; idx += nwarp) {
        int row = zlist[idx];
        float a0 = 0.f, a1 = 0.f, a2 = 0.f, a3 = 0.f;
        const float* brow = B + (size_t)row * RANK;
#pragma unroll 4
        for (int k = 0; k < RANK; k++) {
            float hk = __ldg(brow + k);
            float4 w = *(const float4*)(Wa + (size_t)k * RANK + lane * 4);
            a0 = fmaf(hk, w.x, a0); a1 = fmaf(hk, w.y, a1);
            a2 = fmaf(hk, w.z, a2); a3 = fmaf(hk, w.w, a3);
        }
        float4 v;
        v.x = (a0 >= 0.f) ? a0 : a0 * SLOPE;
        v.y = (a1 >= 0.f) ? a1 : a1 * SLOPE;
        v.z = (a2 >= 0.f) ? a2 : a2 * SLOPE;
        v.w = (a3 >= 0.f) ? a3 : a3 * SLOPE;
        *(float4*)(out + (size_t)row * RANK + lane * 4) = v;
    }
}

// ======================= HMMA (mma.sync) GEMM kernel =======================
// out = leaky( (norm*acc) @ Wn + h @ Wl ), 128x128 tile per CTA, bf16 hi/lo
// split (3 MMA terms) accumulated in fp32 fragments across both halves.

__device__ __forceinline__ uint32_t smem_u32(const void* p) {
    uint32_t a;
    asm("{ .reg .u64 t; cvta.to.shared.u64 t, %1; cvt.u32.u64 %0, t; }" : "=r"(a) : "l"(p));
    return a;
}
__device__ __forceinline__ void ldsm_x4(uint32_t& r0, uint32_t& r1, uint32_t& r2, uint32_t& r3,
                                        uint32_t addr) {
    asm volatile("ldmatrix.sync.aligned.m8n8.x4.shared.b16 {%0,%1,%2,%3}, [%4];"
                 : "=r"(r0), "=r"(r1), "=r"(r2), "=r"(r3) : "r"(addr));
}
__device__ __forceinline__ void ldsm_x4_t(uint32_t& r0, uint32_t& r1, uint32_t& r2, uint32_t& r3,
                                          uint32_t addr) {
    asm volatile("ldmatrix.sync.aligned.m8n8.x4.trans.shared.b16 {%0,%1,%2,%3}, [%4];"
                 : "=r"(r0), "=r"(r1), "=r"(r2), "=r"(r3) : "r"(addr));
}
__device__ __forceinline__ void mma16816(float* c, const uint32_t* a, const uint32_t* b) {
    asm volatile(
        "mma.sync.aligned.m16n8k16.row.col.f32.bf16.bf16.f32 "
        "{%0,%1,%2,%3}, {%4,%5,%6,%7}, {%8,%9}, {%0,%1,%2,%3};"
        : "+f"(c[0]), "+f"(c[1]), "+f"(c[2]), "+f"(c[3])
        : "r"(a[0]), "r"(a[1]), "r"(a[2]), "r"(a[3]), "r"(b[0]), "r"(b[1]));
}

#define TSTRIDE 136                   // bf16 elements per smem row (128 + 8 pad)
#define TILE_B  (128 * TSTRIDE * 2)   // 34816 bytes per tile
#define XHI 0
#define XLO (TILE_B)
#define WHI (2 * TILE_B)
#define WLO (3 * TILE_B)
#define SM_TOTAL (4 * TILE_B)

// split 8 fp32 -> bf16 hi / bf16 lo, store 16B each into two tiles
__device__ __forceinline__ void split_store8(char* sm, uint32_t hi_base, uint32_t lo_base,
                                             uint32_t byteoff, const float* v) {
    uint32_t hp[4], lp[4];
#pragma unroll
    for (int j = 0; j < 4; j++) {
        __nv_bfloat16 h0 = __float2bfloat16(v[2 * j]);
        __nv_bfloat16 h1 = __float2bfloat16(v[2 * j + 1]);
        float l0 = v[2 * j]     - __bfloat162float(h0);
        float l1 = v[2 * j + 1] - __bfloat162float(h1);
        __nv_bfloat16 g0 = __float2bfloat16(l0);
        __nv_bfloat16 g1 = __float2bfloat16(l1);
        hp[j] = (uint32_t)__bfloat16_as_ushort(h0) | ((uint32_t)__bfloat16_as_ushort(h1) << 16);
        lp[j] = (uint32_t)__bfloat16_as_ushort(g0) | ((uint32_t)__bfloat16_as_ushort(g1) << 16);
    }
    *(uint4*)(sm + hi_base + byteoff) = make_uint4(hp[0], hp[1], hp[2], hp[3]);
    *(uint4*)(sm + lo_base + byteoff) = make_uint4(lp[0], lp[1], lp[2], lp[3]);
}

__global__ __launch_bounds__(256, 1)
void gemm_mma_kernel(const float* __restrict__ A,     // acc [NE,128]
                     const float* __restrict__ B,     // h   [NE,128]
                     const float* __restrict__ Wn,    // [128,128], row = k
                     const float* __restrict__ Wl,
                     const float* __restrict__ norm,
                     float* __restrict__ out) {
    extern __shared__ char sm[];
    uint32_t smb = smem_u32(sm);
    int tid    = threadIdx.x;
    int lane   = tid & 31;
    int wid    = tid >> 5;
    int warp_m = wid & 3;     // 32-row band
    int warp_n = wid >> 2;    // 64-col band
    int row0   = blockIdx.x * 128;

    float c[2][8][4];
#pragma unroll
    for (int mf = 0; mf < 2; mf++)
#pragma unroll
        for (int nf = 0; nf < 8; nf++)
#pragma unroll
            for (int q = 0; q < 4; q++) c[mf][nf][q] = 0.f;

#pragma unroll 1
    for (int half = 0; half < 2; half++) {
        const float* X = (half == 0) ? A : B;
        const float* W = (half == 0) ? Wn : Wl;

        // X tile -> Xhi/Xlo  [row][k], row-major, stride 136
#pragma unroll 1
        for (int i = tid; i < 2048; i += 256) {
            int row = i >> 4;
            int k0  = (i & 15) << 3;
            int grow = row0 + row;
            float v[8];
            if (grow < NE) {
                float4 x0 = *(const float4*)(X + (size_t)grow * RANK + k0);
                float4 x1 = *(const float4*)(X + (size_t)grow * RANK + k0 + 4);
                float s = (half == 0) ? __ldg(norm + grow) : 1.0f;
                v[0] = x0.x * s; v[1] = x0.y * s; v[2] = x0.z * s; v[3] = x0.w * s;
                v[4] = x1.x * s; v[5] = x1.y * s; v[6] = x1.z * s; v[7] = x1.w * s;
            } else {
#pragma unroll
                for (int j = 0; j < 8; j++) v[j] = 0.f;
            }
            split_store8(sm, XHI, XLO, (uint32_t)(row * TSTRIDE + k0) * 2, v);
        }

        // W tile -> Whi/Wlo  [k][n], row-major (ldmatrix.trans provides col-major B)
#pragma unroll 1
        for (int i = tid; i < 2048; i += 256) {
            int k  = i >> 4;
            int n0 = (i & 15) << 3;
            float v[8];
            float4 w0 = *(const float4*)(W + (size_t)k * RANK + n0);
            float4 w1 = *(const float4*)(W + (size_t)k * RANK + n0 + 4);
            v[0] = w0.x; v[1] = w0.y; v[2] = w0.z; v[3] = w0.w;
            v[4] = w1.x; v[5] = w1.y; v[6] = w1.z; v[7] = w1.w;
            split_store8(sm, WHI, WLO, (uint32_t)(k * TSTRIDE + n0) * 2, v);
        }
        __syncthreads();

#pragma unroll 1
        for (int ks = 0; ks < 8; ks++) {
            int k0 = ks * 16;
            // A fragments (hi, lo) for 2 m16 blocks
            uint32_t aH[2][4], aL[2][4];
#pragma unroll
            for (int mf = 0; mf < 2; mf++) {
                int row = warp_m * 32 + mf * 16 + (lane & 15);
                int col = k0 + (lane >> 4) * 8;
                uint32_t off = (uint32_t)(row * TSTRIDE + col) * 2;
                ldsm_x4(aH[mf][0], aH[mf][1], aH[mf][2], aH[mf][3], smb + XHI + off);
                ldsm_x4(aL[mf][0], aL[mf][1], aL[mf][2], aL[mf][3], smb + XLO + off);
            }
            // B fragments (hi, lo) for 8 n8 blocks
            uint32_t bH[8][2], bL[8][2];
#pragma unroll
            for (int nb = 0; nb < 4; nb++) {
                int n0   = warp_n * 64 + nb * 16;
                int krow = k0 + ((lane >> 3) & 1) * 8 + (lane & 7);
                int ncol = n0 + (lane >> 4) * 8;
                uint32_t off = (uint32_t)(krow * TSTRIDE + ncol) * 2;
                uint32_t r0, r1, r2, r3;
                ldsm_x4_t(r0, r1, r2, r3, smb + WHI + off);
                bH[nb * 2][0] = r0; bH[nb * 2][1] = r1;
                bH[nb * 2 + 1][0] = r2; bH[nb * 2 + 1][1] = r3;
                ldsm_x4_t(r0, r1, r2, r3, smb + WLO + off);
                bL[nb * 2][0] = r0; bL[nb * 2][1] = r1;
                bL[nb * 2 + 1][0] = r2; bL[nb * 2 + 1][1] = r3;
            }
#pragma unroll
            for (int mf = 0; mf < 2; mf++)
#pragma unroll
                for (int nf = 0; nf < 8; nf++) {
                    mma16816(c[mf][nf], aH[mf], bH[nf]);   // hi*hi
                    mma16816(c[mf][nf], aH[mf], bL[nf]);   // hi*lo
                    mma16816(c[mf][nf], aL[mf], bH[nf]);   // lo*hi
                }
        }
        __syncthreads();
    }

    // ---------- epilogue: leaky relu + store ----------
    int r_in  = lane >> 2;
    int c_in  = (lane & 3) * 2;
#pragma unroll
    for (int mf = 0; mf < 2; mf++) {
        int rbase = row0 + warp_m * 32 + mf * 16 + r_in;
#pragma unroll
        for (int nf = 0; nf < 8; nf++) {
            int col = warp_n * 64 + nf * 8 + c_in;
            float x0 = c[mf][nf][0], x1 = c[mf][nf][1];
            float x2 = c[mf][nf][2], x3 = c[mf][nf][3];
            x0 = (x0 >= 0.f) ? x0 : x0 * SLOPE;
            x1 = (x1 >= 0.f) ? x1 : x1 * SLOPE;
            x2 = (x2 >= 0.f) ? x2 : x2 * SLOPE;
            x3 = (x3 >= 0.f) ? x3 : x3 * SLOPE;
            if (rbase < NE)
                *(float2*)(out + (size_t)rbase * RANK + col) = make_float2(x0, x1);
            if (rbase + 8 < NE)
                *(float2*)(out + (size_t)(rbase + 8) * RANK + col) = make_float2(x2, x3);
        }
    }
}

// ======================= launch =======================
extern "C" void kernel_launch(void* const* d_in, const int* in_sizes, int n_in,
                              void* d_out, int out_size) {
    const float* ent  = (const float*)d_in[0];
    const float* rel  = (const float*)d_in[1];
    const float* norm = (const float*)d_in[2];
    const float* Wn   = (const float*)d_in[3];
    const float* Wl   = (const float*)d_in[4];
    const float* Wa   = (const float*)d_in[5];
    const int*   src  = (const int*)d_in[6];
    const int*   dst  = (const int*)d_in[7];
    const int*   et   = (const int*)d_in[8];
    float* out = (float*)d_out;

    void *p_h2, *p_acc, *p_hasin, *p_zlist, *p_zcount;
    cudaGetSymbolAddress(&p_h2, g_h2);
    cudaGetSymbolAddress(&p_acc, g_acc);
    cudaGetSymbolAddress(&p_hasin, g_hasin);
    cudaGetSymbolAddress(&p_zlist, g_zlist);
    cudaGetSymbolAddress(&p_zcount, g_zcount);
    float* h2   = (float*)p_h2;
    float* acc  = (float*)p_acc;
    int* hasin  = (int*)p_hasin;
    int* zlist  = (int*)p_zlist;
    int* zcount = (int*)p_zcount;

    const int WOFF = RANK * RANK;  // per-layer weight offset

    cudaFuncSetAttribute(gemm_mma_kernel, cudaFuncAttributeMaxDynamicSharedMemorySize, SM_TOTAL);

    cudaMemsetAsync(hasin, 0, NE * sizeof(int), 0);
    cudaMemsetAsync(zcount, 0, sizeof(int), 0);
    mark_hasin_kernel<<<(EDGES + 255) / 256, 256>>>(dst, hasin);
    build_zlist_kernel<<<(NE + 255) / 256, 256>>>(hasin, zlist, zcount);

    const int tiles = (NE + 127) / 128;

    // ---- layer 0: h = ent_emb ----
    cudaMemsetAsync(acc, 0, (size_t)NE * RANK * sizeof(float), 0);
    scatter_kernel<<<2048, 256>>>(ent, rel, src, dst, et, acc);
    gemm_mma_kernel<<<tiles, 256, SM_TOTAL>>>(acc, ent, Wn, Wl, norm, h2);
    fixup_kernel<<<32, 256>>>(ent, Wa, zlist, zcount, h2);

    // ---- layer 1: h = h2, write final output ----
    cudaMemsetAsync(acc, 0, (size_t)NE * RANK * sizeof(float), 0);
    scatter_kernel<<<2048, 256>>>(h2, rel, src, dst, et, acc);
    gemm_mma_kernel<<<tiles, 256, SM_TOTAL>>>(acc, h2, Wn + WOFF, Wl + WOFF, norm, out);
    fixup_kernel<<<32, 256>>>(h2, Wa + WOFF, zlist, zcount, out);
}

// round 7
// speedup vs baseline: 1.5576x; 1.1022x over previous
#include <cuda_runtime.h>
#include <cuda_bf16.h>
#include <cstdint>

#define NE 50000
#define EDGES 500000
#define NREL 200
#define RANK 128
#define SLOPE 0.22916666666666666f   // (1/8 + 1/3)/2

// ---------------- scratch (device globals; no allocation allowed) ----------------
__device__ float g_h2[NE * RANK];    // hidden state after layer 0
__device__ float g_acc[NE * RANK];   // scatter accumulator
__device__ int   g_hasin[NE];        // in-degree > 0 mask
__device__ int   g_zlist[NE];        // rows with in-degree == 0
__device__ int   g_zcount;

// ======================= small helper kernels =======================

__global__ void mark_hasin_kernel(const int* __restrict__ dst, int* __restrict__ hasin) {
    int i = blockIdx.x * blockDim.x + threadIdx.x;
    if (i < EDGES) hasin[dst[i]] = 1;
}

__global__ void build_zlist_kernel(const int* __restrict__ hasin,
                                   int* __restrict__ zlist, int* __restrict__ zcount) {
    int i = blockIdx.x * blockDim.x + threadIdx.x;
    if (i < NE && !hasin[i]) {
        int p = atomicAdd(zcount, 1);
        zlist[p] = i;
    }
}

// acc[dst] += h[src] + rel[etype]   (one warp per edge, red.global.v4.f32)
__global__ void scatter_kernel(const float* __restrict__ h,
                               const float* __restrict__ rel,
                               const int* __restrict__ src,
                               const int* __restrict__ dst,
                               const int* __restrict__ et,
                               float* __restrict__ acc) {
    int lane  = threadIdx.x & 31;
    int warp  = (blockIdx.x * blockDim.x + threadIdx.x) >> 5;
    int nwarp = (gridDim.x * blockDim.x) >> 5;
    int col   = lane * 4;
    for (int e = warp; e < EDGES; e += nwarp) {
        int s = src[e], d = dst[e], t = et[e];
        float4 hv = *(const float4*)(h   + (size_t)s * RANK + col);
        float4 rv = *(const float4*)(rel + (size_t)t * RANK + col);
        float4 v;
        v.x = hv.x + rv.x; v.y = hv.y + rv.y; v.z = hv.z + rv.z; v.w = hv.w + rv.w;
        float* p = acc + (size_t)d * RANK + col;
        asm volatile("red.global.add.v4.f32 [%0], {%1, %2, %3, %4};"
                     :: "l"(p), "f"(v.x), "f"(v.y), "f"(v.z), "f"(v.w) : "memory");
    }
}

// Rows with in_deg==0 (expected ~2): out[row] = leaky(h[row] @ Wa)
__global__ void fixup_kernel(const float* __restrict__ B,
                             const float* __restrict__ Wa,
                             const int* __restrict__ zlist,
                             const int* __restrict__ zcount,
                             float* __restrict__ out) {
    int lane  = threadIdx.x & 31;
    int warp  = (blockIdx.x * blockDim.x + threadIdx.x) >> 5;
    int nwarp = (gridDim.x * blockDim.x) >> 5;
    int cnt   = *zcount;
    for (int idx = warp; idx < cnt; idx += nwarp) {
        int row = zlist[idx];
        float a0 = 0.f, a1 = 0.f, a2 = 0.f, a3 = 0.f;
        const float* brow = B + (size_t)row * RANK;
#pragma unroll 4
        for (int k = 0; k < RANK; k++) {
            float hk = __ldg(brow + k);
            float4 w = *(const float4*)(Wa + (size_t)k * RANK + lane * 4);
            a0 = fmaf(hk, w.x, a0); a1 = fmaf(hk, w.y, a1);
            a2 = fmaf(hk, w.z, a2); a3 = fmaf(hk, w.w, a3);
        }
        float4 v;
        v.x = (a0 >= 0.f) ? a0 : a0 * SLOPE;
        v.y = (a1 >= 0.f) ? a1 : a1 * SLOPE;
        v.z = (a2 >= 0.f) ? a2 : a2 * SLOPE;
        v.w = (a3 >= 0.f) ? a3 : a3 * SLOPE;
        *(float4*)(out + (size_t)row * RANK + lane * 4) = v;
    }
}

// ======================= HMMA (mma.sync) GEMM kernel =======================
// out = leaky( (norm*acc) @ Wn + h @ Wl ), 64x128 tile per CTA, bf16 hi/lo
// split (3 MMA terms) accumulated in fp32 fragments across both halves.
// 2 CTAs/SM so one CTA's MMA phase overlaps the other's load/convert phase.

__device__ __forceinline__ uint32_t smem_u32(const void* p) {
    uint32_t a;
    asm("{ .reg .u64 t; cvta.to.shared.u64 t, %1; cvt.u32.u64 %0, t; }" : "=r"(a) : "l"(p));
    return a;
}
__device__ __forceinline__ void ldsm_x4(uint32_t& r0, uint32_t& r1, uint32_t& r2, uint32_t& r3,
                                        uint32_t addr) {
    asm volatile("ldmatrix.sync.aligned.m8n8.x4.shared.b16 {%0,%1,%2,%3}, [%4];"
                 : "=r"(r0), "=r"(r1), "=r"(r2), "=r"(r3) : "r"(addr));
}
__device__ __forceinline__ void ldsm_x4_t(uint32_t& r0, uint32_t& r1, uint32_t& r2, uint32_t& r3,
                                          uint32_t addr) {
    asm volatile("ldmatrix.sync.aligned.m8n8.x4.trans.shared.b16 {%0,%1,%2,%3}, [%4];"
                 : "=r"(r0), "=r"(r1), "=r"(r2), "=r"(r3) : "r"(addr));
}
__device__ __forceinline__ void mma16816(float* c, const uint32_t* a, const uint32_t* b) {
    asm volatile(
        "mma.sync.aligned.m16n8k16.row.col.f32.bf16.bf16.f32 "
        "{%0,%1,%2,%3}, {%4,%5,%6,%7}, {%8,%9}, {%0,%1,%2,%3};"
        : "+f"(c[0]), "+f"(c[1]), "+f"(c[2]), "+f"(c[3])
        : "r"(a[0]), "r"(a[1]), "r"(a[2]), "r"(a[3]), "r"(b[0]), "r"(b[1]));
}

#define TSTRIDE 136                     // bf16 elements per smem row (128 + 8 pad)
#define XTILE_B (64 * TSTRIDE * 2)      // 17408 bytes (64-row X tile)
#define WTILE_B (128 * TSTRIDE * 2)     // 34816 bytes (128-row W tile)
#define XHI 0
#define XLO (XTILE_B)
#define WHI (2 * XTILE_B)
#define WLO (2 * XTILE_B + WTILE_B)
#define SM_TOTAL (2 * XTILE_B + 2 * WTILE_B)   // 104448 bytes -> 2 CTAs/SM

// split 8 fp32 -> bf16 hi / bf16 lo, store 16B each into two tiles
__device__ __forceinline__ void split_store8(char* sm, uint32_t hi_base, uint32_t lo_base,
                                             uint32_t byteoff, const float* v) {
    uint32_t hp[4], lp[4];
#pragma unroll
    for (int j = 0; j < 4; j++) {
        __nv_bfloat16 h0 = __float2bfloat16(v[2 * j]);
        __nv_bfloat16 h1 = __float2bfloat16(v[2 * j + 1]);
        float l0 = v[2 * j]     - __bfloat162float(h0);
        float l1 = v[2 * j + 1] - __bfloat162float(h1);
        __nv_bfloat16 g0 = __float2bfloat16(l0);
        __nv_bfloat16 g1 = __float2bfloat16(l1);
        hp[j] = (uint32_t)__bfloat16_as_ushort(h0) | ((uint32_t)__bfloat16_as_ushort(h1) << 16);
        lp[j] = (uint32_t)__bfloat16_as_ushort(g0) | ((uint32_t)__bfloat16_as_ushort(g1) << 16);
    }
    *(uint4*)(sm + hi_base + byteoff) = make_uint4(hp[0], hp[1], hp[2], hp[3]);
    *(uint4*)(sm + lo_base + byteoff) = make_uint4(lp[0], lp[1], lp[2], lp[3]);
}

__global__ __launch_bounds__(256, 2)
void gemm_mma_kernel(const float* __restrict__ A,     // acc [NE,128]
                     const float* __restrict__ B,     // h   [NE,128]
                     const float* __restrict__ Wn,    // [128,128], row = k
                     const float* __restrict__ Wl,
                     const float* __restrict__ norm,
                     float* __restrict__ out) {
    extern __shared__ char sm[];
    uint32_t smb = smem_u32(sm);
    int tid    = threadIdx.x;
    int lane   = tid & 31;
    int wid    = tid >> 5;
    int warp_m = wid & 1;     // 32-row band within the 64-row tile
    int warp_n = wid >> 1;    // 32-col band (4 warps cover N=128)
    int row0   = blockIdx.x * 64;

    float c[2][4][4];
#pragma unroll
    for (int mf = 0; mf < 2; mf++)
#pragma unroll
        for (int nf = 0; nf < 4; nf++)
#pragma unroll
            for (int q = 0; q < 4; q++) c[mf][nf][q] = 0.f;

#pragma unroll 1
    for (int half = 0; half < 2; half++) {
        const float* X = (half == 0) ? A : B;
        const float* W = (half == 0) ? Wn : Wl;

        // X tile -> Xhi/Xlo  [row][k], row-major, stride 136 (64 rows x 16 kchunks)
#pragma unroll 1
        for (int i = tid; i < 1024; i += 256) {
            int row = i >> 4;
            int k0  = (i & 15) << 3;
            int grow = row0 + row;
            float v[8];
            if (grow < NE) {
                float4 x0 = *(const float4*)(X + (size_t)grow * RANK + k0);
                float4 x1 = *(const float4*)(X + (size_t)grow * RANK + k0 + 4);
                float s = (half == 0) ? __ldg(norm + grow) : 1.0f;
                v[0] = x0.x * s; v[1] = x0.y * s; v[2] = x0.z * s; v[3] = x0.w * s;
                v[4] = x1.x * s; v[5] = x1.y * s; v[6] = x1.z * s; v[7] = x1.w * s;
            } else {
#pragma unroll
                for (int j = 0; j < 8; j++) v[j] = 0.f;
            }
            split_store8(sm, XHI, XLO, (uint32_t)(row * TSTRIDE + k0) * 2, v);
        }

        // W tile -> Whi/Wlo  [k][n], row-major (ldmatrix.trans provides col-major B)
#pragma unroll 1
        for (int i = tid; i < 2048; i += 256) {
            int k  = i >> 4;
            int n0 = (i & 15) << 3;
            float v[8];
            float4 w0 = *(const float4*)(W + (size_t)k * RANK + n0);
            float4 w1 = *(const float4*)(W + (size_t)k * RANK + n0 + 4);
            v[0] = w0.x; v[1] = w0.y; v[2] = w0.z; v[3] = w0.w;
            v[4] = w1.x; v[5] = w1.y; v[6] = w1.z; v[7] = w1.w;
            split_store8(sm, WHI, WLO, (uint32_t)(k * TSTRIDE + n0) * 2, v);
        }
        __syncthreads();

#pragma unroll 1
        for (int ks = 0; ks < 8; ks++) {
            int k0 = ks * 16;
            // A fragments (hi, lo) for 2 m16 blocks
            uint32_t aH[2][4], aL[2][4];
#pragma unroll
            for (int mf = 0; mf < 2; mf++) {
                int row = warp_m * 32 + mf * 16 + (lane & 15);
                int col = k0 + (lane >> 4) * 8;
                uint32_t off = (uint32_t)(row * TSTRIDE + col) * 2;
                ldsm_x4(aH[mf][0], aH[mf][1], aH[mf][2], aH[mf][3], smb + XHI + off);
                ldsm_x4(aL[mf][0], aL[mf][1], aL[mf][2], aL[mf][3], smb + XLO + off);
            }
            // B fragments (hi, lo) for 4 n8 blocks (2 ldmatrix.x4.trans of 16 cols)
            uint32_t bH[4][2], bL[4][2];
#pragma unroll
            for (int nb = 0; nb < 2; nb++) {
                int n0   = warp_n * 32 + nb * 16;
                int krow = k0 + ((lane >> 3) & 1) * 8 + (lane & 7);
                int ncol = n0 + (lane >> 4) * 8;
                uint32_t off = (uint32_t)(krow * TSTRIDE + ncol) * 2;
                uint32_t r0, r1, r2, r3;
                ldsm_x4_t(r0, r1, r2, r3, smb + WHI + off);
                bH[nb * 2][0] = r0; bH[nb * 2][1] = r1;
                bH[nb * 2 + 1][0] = r2; bH[nb * 2 + 1][1] = r3;
                ldsm_x4_t(r0, r1, r2, r3, smb + WLO + off);
                bL[nb * 2][0] = r0; bL[nb * 2][1] = r1;
                bL[nb * 2 + 1][0] = r2; bL[nb * 2 + 1][1] = r3;
            }
#pragma unroll
            for (int mf = 0; mf < 2; mf++)
#pragma unroll
                for (int nf = 0; nf < 4; nf++) {
                    mma16816(c[mf][nf], aH[mf], bH[nf]);   // hi*hi
                    mma16816(c[mf][nf], aH[mf], bL[nf]);   // hi*lo
                    mma16816(c[mf][nf], aL[mf], bH[nf]);   // lo*hi
                }
        }
        __syncthreads();
    }

    // ---------- epilogue: leaky relu + store ----------
    int r_in  = lane >> 2;
    int c_in  = (lane & 3) * 2;
#pragma unroll
    for (int mf = 0; mf < 2; mf++) {
        int rbase = row0 + warp_m * 32 + mf * 16 + r_in;
#pragma unroll
        for (int nf = 0; nf < 4; nf++) {
            int col = warp_n * 32 + nf * 8 + c_in;
            float x0 = c[mf][nf][0], x1 = c[mf][nf][1];
            float x2 = c[mf][nf][2], x3 = c[mf][nf][3];
            x0 = (x0 >= 0.f) ? x0 : x0 * SLOPE;
            x1 = (x1 >= 0.f) ? x1 : x1 * SLOPE;
            x2 = (x2 >= 0.f) ? x2 : x2 * SLOPE;
            x3 = (x3 >= 0.f) ? x3 : x3 * SLOPE;
            if (rbase < NE)
                *(float2*)(out + (size_t)rbase * RANK + col) = make_float2(x0, x1);
            if (rbase + 8 < NE)
                *(float2*)(out + (size_t)(rbase + 8) * RANK + col) = make_float2(x2, x3);
        }
    }
}

// ======================= launch =======================
extern "C" void kernel_launch(void* const* d_in, const int* in_sizes, int n_in,
                              void* d_out, int out_size) {
    const float* ent  = (const float*)d_in[0];
    const float* rel  = (const float*)d_in[1];
    const float* norm = (const float*)d_in[2];
    const float* Wn   = (const float*)d_in[3];
    const float* Wl   = (const float*)d_in[4];
    const float* Wa   = (const float*)d_in[5];
    const int*   src  = (const int*)d_in[6];
    const int*   dst  = (const int*)d_in[7];
    const int*   et   = (const int*)d_in[8];
    float* out = (float*)d_out;

    void *p_h2, *p_acc, *p_hasin, *p_zlist, *p_zcount;
    cudaGetSymbolAddress(&p_h2, g_h2);
    cudaGetSymbolAddress(&p_acc, g_acc);
    cudaGetSymbolAddress(&p_hasin, g_hasin);
    cudaGetSymbolAddress(&p_zlist, g_zlist);
    cudaGetSymbolAddress(&p_zcount, g_zcount);
    float* h2   = (float*)p_h2;
    float* acc  = (float*)p_acc;
    int* hasin  = (int*)p_hasin;
    int* zlist  = (int*)p_zlist;
    int* zcount = (int*)p_zcount;

    const int WOFF = RANK * RANK;  // per-layer weight offset

    cudaFuncSetAttribute(gemm_mma_kernel, cudaFuncAttributeMaxDynamicSharedMemorySize, SM_TOTAL);

    cudaMemsetAsync(hasin, 0, NE * sizeof(int), 0);
    cudaMemsetAsync(zcount, 0, sizeof(int), 0);
    mark_hasin_kernel<<<(EDGES + 255) / 256, 256>>>(dst, hasin);
    build_zlist_kernel<<<(NE + 255) / 256, 256>>>(hasin, zlist, zcount);

    const int tiles = (NE + 63) / 64;

    // ---- layer 0: h = ent_emb ----
    cudaMemsetAsync(acc, 0, (size_t)NE * RANK * sizeof(float), 0);
    scatter_kernel<<<2048, 256>>>(ent, rel, src, dst, et, acc);
    gemm_mma_kernel<<<tiles, 256, SM_TOTAL>>>(acc, ent, Wn, Wl, norm, h2);
    fixup_kernel<<<32, 256>>>(ent, Wa, zlist, zcount, h2);

    // ---- layer 1: h = h2, write final output ----
    cudaMemsetAsync(acc, 0, (size_t)NE * RANK * sizeof(float), 0);
    scatter_kernel<<<2048, 256>>>(h2, rel, src, dst, et, acc);
    gemm_mma_kernel<<<tiles, 256, SM_TOTAL>>>(acc, h2, Wn + WOFF, Wl + WOFF, norm, out);
    fixup_kernel<<<32, 256>>>(h2, Wa + WOFF, zlist, zcount, out);
}